// round 11
// baseline (speedup 1.0000x reference)
#include <cuda_runtime.h>
#include <cuda_bf16.h>
#include <mma.h>
#include <cstdint>
#include <cstddef>

#define N_NODES 50000
#define N_NODES_PAD 50048          // 391 tiles * 128
#define N_EDGES 800000
#define HDIM 128
#define LN_EPS 1e-5f
#define SAW 132                    // nodeproj A smem stride in floats (132 % 32 == 4)
#define N_TILES (N_EDGES / 128)
#define NP_TILES ((N_NODES + 127) / 128)

// Scratch (allocation-free rule: __device__ globals)
__device__ float g_xsxr[(size_t)N_NODES_PAD * 256];  // [n,0:128]=x@Ws, [n,128:256]=x@Wr
__device__ float g_aggr[(size_t)N_NODES * HDIM];

__device__ __forceinline__ float t32(float v) { return nvcuda::wmma::__float_to_tf32(v); }

__device__ __forceinline__ void red_add_v4(float* p, float a, float b, float c, float d) {
    asm volatile("red.global.add.v4.f32 [%0], {%1, %2, %3, %4};"
                 :: "l"(p), "f"(a), "f"(b), "f"(c), "f"(d) : "memory");
}

__device__ __forceinline__ void mma_16n8k8(float* c, const uint32_t* a, const uint32_t* b) {
    asm volatile(
        "mma.sync.aligned.m16n8k8.row.col.f32.tf32.tf32.f32 "
        "{%0,%1,%2,%3}, {%4,%5,%6,%7}, {%8,%9}, {%0,%1,%2,%3};"
        : "+f"(c[0]), "+f"(c[1]), "+f"(c[2]), "+f"(c[3])
        : "r"(a[0]), "r"(a[1]), "r"(a[2]), "r"(a[3]), "r"(b[0]), "r"(b[1]));
}

// B fragment-major staging: value (k,n) of a [K=128][n] weight block.
// frag block (ks=k>>3, nt=n>>3) is 64 floats: lane = (n&7)*4 + (k&3), reg = (k&7)>>2.
__device__ __forceinline__ int bfrag_off(int k, int n, int NT) {
    int ks = k >> 3, nt = n >> 3;
    int lane = ((n & 7) << 2) | (k & 3);
    int reg = (k & 7) >> 2;
    return ((ks * NT + nt) << 6) + lane * 2 + reg;
}

// ---------------------------------------------------------------------------
// Node projection (persistent): XsXr[tile] = x[tile] @ [Ws | Wr]  (unchanged)
// ---------------------------------------------------------------------------
__global__ __launch_bounds__(512, 1)
void nodeproj_kernel(const float* __restrict__ x, const float* __restrict__ W1) {
    extern __shared__ float sm[];
    float* sB = sm;                      // 16 ks * 32 nt * 64 = 32768 floats (frag-major)
    float* sA = sm + 32768;              // 128 x SAW

    const int tid = threadIdx.x;
    const int w = tid >> 5;
    const int lane = tid & 31;
    const int wr = w >> 3;               // 0..1 : 64-row strip
    const int wc = w & 7;                // 0..7 : 32-col strip

    for (int idx = tid; idx < 128 * 256; idx += 512) {
        int k = idx >> 8, n = idx & 255;
        float v = (n < 128) ? W1[(size_t)k * HDIM + n]
                            : W1[(size_t)(128 + k) * HDIM + (n - 128)];
        sB[bfrag_off(k, n, 32)] = t32(v);
    }
    __syncthreads();

    const float2* pB = (const float2*)sB;
    const float* Abase = sA + (wr * 64 + (lane >> 2)) * SAW + (lane & 3);

    for (int t = blockIdx.x; t < NP_TILES; t += gridDim.x) {
        const int rowBase = t * 128;

        for (int idx = tid; idx < 128 * 32; idx += 512) {
            int r = idx >> 5, c4 = idx & 31;
            int gr = rowBase + r;
            float4 v = make_float4(0.f, 0.f, 0.f, 0.f);
            if (gr < N_NODES) v = ((const float4*)(x + (size_t)gr * HDIM))[c4];
            float* d = sA + r * SAW + c4 * 4;
            d[0] = t32(v.x); d[1] = t32(v.y); d[2] = t32(v.z); d[3] = t32(v.w);
        }
        __syncthreads();

        float acc[4][4][4];
        #pragma unroll
        for (int i = 0; i < 4; ++i)
            #pragma unroll
            for (int j = 0; j < 4; ++j)
                acc[i][j][0] = acc[i][j][1] = acc[i][j][2] = acc[i][j][3] = 0.f;

        #pragma unroll
        for (int ks = 0; ks < 16; ++ks) {
            uint32_t a[4][4], b[4][2];
            #pragma unroll
            for (int i = 0; i < 4; ++i) {
                const float* p = Abase + i * (16 * SAW) + ks * 8;
                a[i][0] = __float_as_uint(p[0]);
                a[i][1] = __float_as_uint(p[8 * SAW]);
                a[i][2] = __float_as_uint(p[4]);
                a[i][3] = __float_as_uint(p[8 * SAW + 4]);
            }
            #pragma unroll
            for (int j = 0; j < 4; ++j) {
                float2 bb = pB[(ks * 32 + wc * 4 + j) * 32 + lane];
                b[j][0] = __float_as_uint(bb.x);
                b[j][1] = __float_as_uint(bb.y);
            }
            #pragma unroll
            for (int i = 0; i < 4; ++i)
                #pragma unroll
                for (int j = 0; j < 4; ++j) mma_16n8k8(acc[i][j], a[i], b[j]);
        }

        #pragma unroll
        for (int i = 0; i < 4; ++i) {
            int row = rowBase + wr * 64 + i * 16 + (lane >> 2);
            #pragma unroll
            for (int j = 0; j < 4; ++j) {
                int col = wc * 32 + j * 8 + 2 * (lane & 3);
                *(float2*)(g_xsxr + (size_t)row * 256 + col) =
                    make_float2(acc[i][j][0], acc[i][j][1]);
                *(float2*)(g_xsxr + (size_t)(row + 8) * 256 + col) =
                    make_float2(acc[i][j][2], acc[i][j][3]);
            }
        }
        __syncthreads();
    }
}

// ---------------------------------------------------------------------------
// Fused edge kernel, barrier-free, COLUMN-PERMUTED B:
// We permute the 64 cols of each warp-half inside the B fragments so each
// quad-lane (tq) owns 16 CONSECUTIVE true output columns:
//   frag slot (j = n&7, n_local = 2*((n>>4)&3) + ((n>>3)&1)) holds true col n
//   => c-reg acc[i][j][2h+b]  ->  true col  wc*64 + 16*tq + 8*b + j
// Epilogue: 4 float4 gathers + 4 red.global.add.v4 per edge-row-half
// (halves gather & scatter lane-ops vs R10's float2/red.v2).
// ---------------------------------------------------------------------------
__global__ __launch_bounds__(256, 2)
void edge_kernel(const float* __restrict__ ef,
                 const int* __restrict__ senders,
                 const int* __restrict__ receivers,
                 const float* __restrict__ W1,
                 const float* __restrict__ b1) {
    extern __shared__ float sm[];
    float* sBias = sm;                       // 128
    float* sB = sm + 128;                    // 16 ks * 16 nt * 64 = 16384 (frag-major)

    const int tid = threadIdx.x;
    const int w = tid >> 5;
    const int lane = tid & 31;
    const int wr = w >> 1;                   // 0..3 : 32-edge strip
    const int wc = w & 1;                    // 0..1 : 64-col half
    const int g = lane >> 2;
    const int tq = lane & 3;
    const int colbase = wc * 64 + 16 * tq;   // this thread's 16 true cols

    if (tid < 128) sBias[tid] = b1[tid];
    // stage B = We frag-major with the column permutation described above
    for (int idx = tid; idx < 128 * 128; idx += 256) {
        int k = idx >> 7, n = idx & 127;
        int half = n >> 6, within = n & 63;
        int j = within & 7;
        int b_ = (within >> 3) & 1;
        int tqo = (within >> 4) & 3;
        int n_perm = (half << 6) | (j << 3) | (2 * tqo + b_);
        sB[bfrag_off(k, n_perm, 16)] = t32(W1[(size_t)(256 + k) * HDIM + n]);
    }
    __syncthreads();

    const float2* pB = (const float2*)sB;

    for (int tile = blockIdx.x; tile < N_TILES; tile += gridDim.x) {
        const int base = tile * 128;
        const int row0 = base + wr * 32 + g;

        // edge indices for this thread's 4 rows
        int sarr[4], rarr[4];
        #pragma unroll
        for (int i = 0; i < 2; ++i) {
            sarr[2 * i]     = senders[row0 + i * 16];
            rarr[2 * i]     = receivers[row0 + i * 16];
            sarr[2 * i + 1] = senders[row0 + i * 16 + 8];
            rarr[2 * i + 1] = receivers[row0 + i * 16 + 8];
        }

        // bias for this thread's 16 cols (from smem, transient)
        const float4* bb4 = (const float4*)(sBias + colbase);
        float4 bbv[4];
        #pragma unroll
        for (int q = 0; q < 4; ++q) bbv[q] = bb4[q];

        // gather-init acc = Xs[s] + Xr[r] + b   (4 LDG.128 per row-half pair)
        float acc[2][8][4];
        #pragma unroll
        for (int i = 0; i < 2; ++i) {
            #pragma unroll
            for (int h = 0; h < 2; ++h) {
                const float4* xs4 = (const float4*)(g_xsxr + (size_t)sarr[2 * i + h] * 256 + colbase);
                const float4* xr4 = (const float4*)(g_xsxr + (size_t)rarr[2 * i + h] * 256 + 128 + colbase);
                float4 q0 = xs4[0], q1 = xs4[1], q2 = xs4[2], q3 = xs4[3];
                float4 r0 = xr4[0], r1 = xr4[1], r2 = xr4[2], r3 = xr4[3];
                // cols 0..3  (b=0, j=0..3) -> acc[i][j][2h]
                acc[i][0][2*h] = q0.x + r0.x + bbv[0].x;
                acc[i][1][2*h] = q0.y + r0.y + bbv[0].y;
                acc[i][2][2*h] = q0.z + r0.z + bbv[0].z;
                acc[i][3][2*h] = q0.w + r0.w + bbv[0].w;
                // cols 4..7  (b=0, j=4..7)
                acc[i][4][2*h] = q1.x + r1.x + bbv[1].x;
                acc[i][5][2*h] = q1.y + r1.y + bbv[1].y;
                acc[i][6][2*h] = q1.z + r1.z + bbv[1].z;
                acc[i][7][2*h] = q1.w + r1.w + bbv[1].w;
                // cols 8..11 (b=1, j=0..3) -> acc[i][j][2h+1]
                acc[i][0][2*h+1] = q2.x + r2.x + bbv[2].x;
                acc[i][1][2*h+1] = q2.y + r2.y + bbv[2].y;
                acc[i][2][2*h+1] = q2.z + r2.z + bbv[2].z;
                acc[i][3][2*h+1] = q2.w + r2.w + bbv[2].w;
                // cols 12..15 (b=1, j=4..7)
                acc[i][4][2*h+1] = q3.x + r3.x + bbv[3].x;
                acc[i][5][2*h+1] = q3.y + r3.y + bbv[3].y;
                acc[i][6][2*h+1] = q3.z + r3.z + bbv[3].z;
                acc[i][7][2*h+1] = q3.w + r3.w + bbv[3].w;
            }
        }

        // acc += ef_tile @ We : A frags straight from global, B from smem
        const float* Ab = ef + (size_t)row0 * HDIM + tq;
        #pragma unroll
        for (int ks = 0; ks < 16; ++ks) {
            uint32_t a[2][4], b[8][2];
            #pragma unroll
            for (int i = 0; i < 2; ++i) {
                const float* p = Ab + i * (16 * HDIM) + ks * 8;
                a[i][0] = __float_as_uint(t32(p[0]));
                a[i][1] = __float_as_uint(t32(p[8 * HDIM]));
                a[i][2] = __float_as_uint(t32(p[4]));
                a[i][3] = __float_as_uint(t32(p[8 * HDIM + 4]));
            }
            #pragma unroll
            for (int j = 0; j < 8; ++j) {
                float2 bb = pB[(ks * 16 + wc * 8 + j) * 32 + lane];
                b[j][0] = __float_as_uint(bb.x);
                b[j][1] = __float_as_uint(bb.y);
            }
            #pragma unroll
            for (int i = 0; i < 2; ++i)
                #pragma unroll
                for (int j = 0; j < 8; ++j) mma_16n8k8(acc[i][j], a[i], b[j]);
        }

        // relu + scatter: 4 red.v4 per row (16 consecutive cols)
        #pragma unroll
        for (int i = 0; i < 2; ++i) {
            #pragma unroll
            for (int h = 0; h < 2; ++h) {
                float* dst = g_aggr + (size_t)rarr[2 * i + h] * HDIM + colbase;
                red_add_v4(dst + 0,
                           fmaxf(acc[i][0][2*h], 0.f), fmaxf(acc[i][1][2*h], 0.f),
                           fmaxf(acc[i][2][2*h], 0.f), fmaxf(acc[i][3][2*h], 0.f));
                red_add_v4(dst + 4,
                           fmaxf(acc[i][4][2*h], 0.f), fmaxf(acc[i][5][2*h], 0.f),
                           fmaxf(acc[i][6][2*h], 0.f), fmaxf(acc[i][7][2*h], 0.f));
                red_add_v4(dst + 8,
                           fmaxf(acc[i][0][2*h+1], 0.f), fmaxf(acc[i][1][2*h+1], 0.f),
                           fmaxf(acc[i][2][2*h+1], 0.f), fmaxf(acc[i][3][2*h+1], 0.f));
                red_add_v4(dst + 12,
                           fmaxf(acc[i][4][2*h+1], 0.f), fmaxf(acc[i][5][2*h+1], 0.f),
                           fmaxf(acc[i][6][2*h+1], 0.f), fmaxf(acc[i][7][2*h+1], 0.f));
            }
        }
    }
}

// ---------------------------------------------------------------------------
// LayerNorm: out = gamma * (h - mu) * rsqrt(var + eps) + beta, h = aggr + x
// ---------------------------------------------------------------------------
__global__ __launch_bounds__(256)
void ln_kernel(const float* __restrict__ x,
               const float* __restrict__ gamma,
               const float* __restrict__ beta,
               float* __restrict__ out) {
    const int gwarp = (blockIdx.x * blockDim.x + threadIdx.x) >> 5;
    const int lane = threadIdx.x & 31;
    if (gwarp >= N_NODES) return;

    const int c = lane * 4;
    float4 ag = *(const float4*)(g_aggr + (size_t)gwarp * HDIM + c);
    float4 xv = *(const float4*)(x + (size_t)gwarp * HDIM + c);
    float4 h = make_float4(ag.x + xv.x, ag.y + xv.y, ag.z + xv.z, ag.w + xv.w);

    float s = h.x + h.y + h.z + h.w;
    float ss = h.x * h.x + h.y * h.y + h.z * h.z + h.w * h.w;
    #pragma unroll
    for (int off = 16; off > 0; off >>= 1) {
        s += __shfl_xor_sync(0xffffffff, s, off);
        ss += __shfl_xor_sync(0xffffffff, ss, off);
    }
    const float mean = s * (1.f / HDIM);
    const float var = ss * (1.f / HDIM) - mean * mean;
    const float inv = rsqrtf(var + LN_EPS);

    float4 g = *(const float4*)(gamma + c);
    float4 b = *(const float4*)(beta + c);
    float4 o;
    o.x = g.x * (h.x - mean) * inv + b.x;
    o.y = g.y * (h.y - mean) * inv + b.y;
    o.z = g.z * (h.z - mean) * inv + b.z;
    o.w = g.w * (h.w - mean) * inv + b.w;
    *(float4*)(out + (size_t)gwarp * HDIM + c) = o;
}

// ---------------------------------------------------------------------------
extern "C" void kernel_launch(void* const* d_in, const int* in_sizes, int n_in,
                              void* d_out, int out_size) {
    const float* x         = (const float*)d_in[0];
    const int*   senders   = (const int*)d_in[1];
    const int*   receivers = (const int*)d_in[2];
    const float* ef        = (const float*)d_in[3];
    const float* W1        = (const float*)d_in[4];
    const float* b1        = (const float*)d_in[5];
    const float* gamma     = (const float*)d_in[6];
    const float* beta      = (const float*)d_in[7];
    float* out = (float*)d_out;

    void* aggr_ptr = nullptr;
    cudaGetSymbolAddress(&aggr_ptr, g_aggr);
    cudaMemsetAsync(aggr_ptr, 0, (size_t)N_NODES * HDIM * sizeof(float), 0);

    const size_t smem_np = (size_t)(32768 + 128 * SAW) * sizeof(float);   // ~199 KB
    const size_t smem_ed = (size_t)(128 + 16384) * sizeof(float);         // 66 KB -> 2 CTAs/SM
    cudaFuncSetAttribute(nodeproj_kernel, cudaFuncAttributeMaxDynamicSharedMemorySize, (int)smem_np);
    cudaFuncSetAttribute(edge_kernel, cudaFuncAttributeMaxDynamicSharedMemorySize, (int)smem_ed);

    nodeproj_kernel<<<148, 512, smem_np>>>(x, W1);
    edge_kernel<<<296, 256, smem_ed>>>(ef, senders, receivers, W1, b1);
    ln_kernel<<<(N_NODES + 7) / 8, 256>>>(x, gamma, beta, out);
}

// round 12
// speedup vs baseline: 1.3554x; 1.3554x over previous
#include <cuda_runtime.h>
#include <cuda_bf16.h>
#include <mma.h>
#include <cstdint>
#include <cstddef>

#define N_NODES 50000
#define N_NODES_PAD 50048          // 391 tiles * 128
#define N_EDGES 800000
#define HDIM 128
#define LN_EPS 1e-5f
#define SAW 132                    // nodeproj A smem stride in floats (132 % 32 == 4)
#define N_TILES (N_EDGES / 128)
#define NP_TILES ((N_NODES + 127) / 128)

// Scratch (allocation-free rule: __device__ globals)
__device__ float g_xsxr[(size_t)N_NODES_PAD * 256];  // [n,0:128]=x@Ws, [n,128:256]=x@Wr
__device__ float g_aggr[(size_t)N_NODES * HDIM];

__device__ __forceinline__ float t32(float v) { return nvcuda::wmma::__float_to_tf32(v); }

__device__ __forceinline__ void red_add_v2(float* p, float a, float b) {
    asm volatile("red.global.add.v2.f32 [%0], {%1, %2};"
                 :: "l"(p), "f"(a), "f"(b) : "memory");
}

__device__ __forceinline__ void mma_16n8k8(float* c, const uint32_t* a, const uint32_t* b) {
    asm volatile(
        "mma.sync.aligned.m16n8k8.row.col.f32.tf32.tf32.f32 "
        "{%0,%1,%2,%3}, {%4,%5,%6,%7}, {%8,%9}, {%0,%1,%2,%3};"
        : "+f"(c[0]), "+f"(c[1]), "+f"(c[2]), "+f"(c[3])
        : "r"(a[0]), "r"(a[1]), "r"(a[2]), "r"(a[3]), "r"(b[0]), "r"(b[1]));
}

// B fragment-major staging: frag block (ks=k>>3, nt=n>>3) is 64 floats:
// lane = (n&7)*4 + (k&3), reg = (k&7)>>2.
__device__ __forceinline__ int bfrag_off(int k, int n, int NT) {
    int ks = k >> 3, nt = n >> 3;
    int lane = ((n & 7) << 2) | (k & 3);
    int reg = (k & 7) >> 2;
    return ((ks * NT + nt) << 6) + lane * 2 + reg;
}

// K-permutation for the edge kernel (A loads become LDG.128):
// true col 16p + 4*tq + e  ->  frag 2p + (e>>1), slot tq + 4*(e&1)
__device__ __forceinline__ int kperm(int k) {
    int p = k >> 4, k16 = k & 15;
    int tq = k16 >> 2, e = k16 & 3;
    int f = 2 * p + (e >> 1);
    int slot = tq + 4 * (e & 1);
    return 8 * f + slot;
}

// ---------------------------------------------------------------------------
// Node projection (persistent): XsXr[tile] = x[tile] @ [Ws | Wr]  (unchanged)
// ---------------------------------------------------------------------------
__global__ __launch_bounds__(512, 1)
void nodeproj_kernel(const float* __restrict__ x, const float* __restrict__ W1) {
    extern __shared__ float sm[];
    float* sB = sm;                      // 16 ks * 32 nt * 64 = 32768 floats (frag-major)
    float* sA = sm + 32768;              // 128 x SAW

    const int tid = threadIdx.x;
    const int w = tid >> 5;
    const int lane = tid & 31;
    const int wr = w >> 3;               // 0..1 : 64-row strip
    const int wc = w & 7;                // 0..7 : 32-col strip

    for (int idx = tid; idx < 128 * 256; idx += 512) {
        int k = idx >> 8, n = idx & 255;
        float v = (n < 128) ? W1[(size_t)k * HDIM + n]
                            : W1[(size_t)(128 + k) * HDIM + (n - 128)];
        sB[bfrag_off(k, n, 32)] = t32(v);
    }
    __syncthreads();

    const float2* pB = (const float2*)sB;
    const float* Abase = sA + (wr * 64 + (lane >> 2)) * SAW + (lane & 3);

    for (int t = blockIdx.x; t < NP_TILES; t += gridDim.x) {
        const int rowBase = t * 128;

        for (int idx = tid; idx < 128 * 32; idx += 512) {
            int r = idx >> 5, c4 = idx & 31;
            int gr = rowBase + r;
            float4 v = make_float4(0.f, 0.f, 0.f, 0.f);
            if (gr < N_NODES) v = ((const float4*)(x + (size_t)gr * HDIM))[c4];
            float* d = sA + r * SAW + c4 * 4;
            d[0] = t32(v.x); d[1] = t32(v.y); d[2] = t32(v.z); d[3] = t32(v.w);
        }
        __syncthreads();

        float acc[4][4][4];
        #pragma unroll
        for (int i = 0; i < 4; ++i)
            #pragma unroll
            for (int j = 0; j < 4; ++j)
                acc[i][j][0] = acc[i][j][1] = acc[i][j][2] = acc[i][j][3] = 0.f;

        #pragma unroll
        for (int ks = 0; ks < 16; ++ks) {
            uint32_t a[4][4], b[4][2];
            #pragma unroll
            for (int i = 0; i < 4; ++i) {
                const float* p = Abase + i * (16 * SAW) + ks * 8;
                a[i][0] = __float_as_uint(p[0]);
                a[i][1] = __float_as_uint(p[8 * SAW]);
                a[i][2] = __float_as_uint(p[4]);
                a[i][3] = __float_as_uint(p[8 * SAW + 4]);
            }
            #pragma unroll
            for (int j = 0; j < 4; ++j) {
                float2 bb = pB[(ks * 32 + wc * 4 + j) * 32 + lane];
                b[j][0] = __float_as_uint(bb.x);
                b[j][1] = __float_as_uint(bb.y);
            }
            #pragma unroll
            for (int i = 0; i < 4; ++i)
                #pragma unroll
                for (int j = 0; j < 4; ++j) mma_16n8k8(acc[i][j], a[i], b[j]);
        }

        #pragma unroll
        for (int i = 0; i < 4; ++i) {
            int row = rowBase + wr * 64 + i * 16 + (lane >> 2);
            #pragma unroll
            for (int j = 0; j < 4; ++j) {
                int col = wc * 32 + j * 8 + 2 * (lane & 3);
                *(float2*)(g_xsxr + (size_t)row * 256 + col) =
                    make_float2(acc[i][j][0], acc[i][j][1]);
                *(float2*)(g_xsxr + (size_t)(row + 8) * 256 + col) =
                    make_float2(acc[i][j][2], acc[i][j][3]);
            }
        }
        __syncthreads();
    }
}

// ---------------------------------------------------------------------------
// Fused edge kernel (barrier-free, K-PERMUTED A/B):
// 256 thr = 8 independent warps, warp tile 32 edges x 64 cols, 2 CTAs/SM.
// A fragments for a kstep-PAIR load as ONE float4 (LDG.128, full sectors)
// per row-half: v = ef[row][16p + 4*tq .. +3]; ks=2p gets {v.x,v.y} (slots
// tq,tq+4), ks=2p+1 gets {v.z,v.w}. B staged in smem with matching kperm.
// Epilogue identical to R10 (float2 gather-init, red.v2 scatter).
// ---------------------------------------------------------------------------
__global__ __launch_bounds__(256, 2)
void edge_kernel(const float* __restrict__ ef,
                 const int* __restrict__ senders,
                 const int* __restrict__ receivers,
                 const float* __restrict__ W1,
                 const float* __restrict__ b1) {
    extern __shared__ float sm[];
    float* sBias = sm;                       // 128
    float* sB = sm + 128;                    // 16 ks * 16 nt * 64 = 16384 (frag-major)

    const int tid = threadIdx.x;
    const int w = tid >> 5;
    const int lane = tid & 31;
    const int wr = w >> 1;                   // 0..3 : 32-edge strip
    const int wc = w & 1;                    // 0..1 : 64-col half
    const int g = lane >> 2;
    const int tq = lane & 3;
    const int t2 = 2 * tq;

    if (tid < 128) sBias[tid] = b1[tid];
    // stage B = We frag-major with the K permutation
    for (int idx = tid; idx < 128 * 128; idx += 256) {
        int k = idx >> 7, n = idx & 127;
        sB[bfrag_off(kperm(k), n, 16)] = t32(W1[(size_t)(256 + k) * HDIM + n]);
    }
    __syncthreads();

    const float2* pB = (const float2*)sB;

    for (int tile = blockIdx.x; tile < N_TILES; tile += gridDim.x) {
        const int base = tile * 128;
        const int row0 = base + wr * 32 + g;

        // edge indices for this thread's 4 rows
        int sarr[4], rarr[4];
        #pragma unroll
        for (int i = 0; i < 2; ++i) {
            sarr[2 * i]     = senders[row0 + i * 16];
            rarr[2 * i]     = receivers[row0 + i * 16];
            sarr[2 * i + 1] = senders[row0 + i * 16 + 8];
            rarr[2 * i + 1] = receivers[row0 + i * 16 + 8];
        }

        // gather-init acc = Xs[s] + Xr[r] + b  (R10 epilogue layout)
        float acc[2][8][4];
        #pragma unroll
        for (int i = 0; i < 2; ++i) {
            #pragma unroll
            for (int h = 0; h < 2; ++h) {
                const float* xsp = g_xsxr + (size_t)sarr[2 * i + h] * 256;
                const float* xrp = g_xsxr + (size_t)rarr[2 * i + h] * 256 + 128;
                #pragma unroll
                for (int j = 0; j < 8; ++j) {
                    int col = wc * 64 + j * 8 + t2;
                    float2 a_ = *(const float2*)(xsp + col);
                    float2 b_ = *(const float2*)(xrp + col);
                    float2 bb = *(const float2*)(sBias + col);
                    acc[i][j][2 * h]     = a_.x + b_.x + bb.x;
                    acc[i][j][2 * h + 1] = a_.y + b_.y + bb.y;
                }
            }
        }

        // acc += ef_tile @ We : A as LDG.128 per kstep-pair, B from smem
        const float* Ab = ef + (size_t)row0 * HDIM + 4 * tq;
        #pragma unroll
        for (int p = 0; p < 8; ++p) {
            float4 v[2][2];   // [i][row-half]
            #pragma unroll
            for (int i = 0; i < 2; ++i) {
                v[i][0] = *(const float4*)(Ab + i * (16 * HDIM) + 16 * p);
                v[i][1] = *(const float4*)(Ab + i * (16 * HDIM) + 8 * HDIM + 16 * p);
            }
            #pragma unroll
            for (int half = 0; half < 2; ++half) {   // ks = 2p + half
                int ks = 2 * p + half;
                uint32_t a[2][4], b[8][2];
                #pragma unroll
                for (int i = 0; i < 2; ++i) {
                    float e0 = half ? v[i][0].z : v[i][0].x;
                    float e1 = half ? v[i][0].w : v[i][0].y;
                    float f0 = half ? v[i][1].z : v[i][1].x;
                    float f1 = half ? v[i][1].w : v[i][1].y;
                    a[i][0] = __float_as_uint(t32(e0));   // slot tq,   row g
                    a[i][1] = __float_as_uint(t32(f0));   // slot tq,   row g+8
                    a[i][2] = __float_as_uint(t32(e1));   // slot tq+4, row g
                    a[i][3] = __float_as_uint(t32(f1));   // slot tq+4, row g+8
                }
                #pragma unroll
                for (int j = 0; j < 8; ++j) {
                    float2 bb = pB[(ks * 16 + wc * 8 + j) * 32 + lane];
                    b[j][0] = __float_as_uint(bb.x);
                    b[j][1] = __float_as_uint(bb.y);
                }
                #pragma unroll
                for (int i = 0; i < 2; ++i)
                    #pragma unroll
                    for (int j = 0; j < 8; ++j) mma_16n8k8(acc[i][j], a[i], b[j]);
            }
        }

        // relu + scatter straight from acc regs (R10 epilogue)
        #pragma unroll
        for (int i = 0; i < 2; ++i) {
            #pragma unroll
            for (int h = 0; h < 2; ++h) {
                float* dst = g_aggr + (size_t)rarr[2 * i + h] * HDIM;
                #pragma unroll
                for (int j = 0; j < 8; ++j) {
                    int col = wc * 64 + j * 8 + t2;
                    float v0 = fmaxf(acc[i][j][2 * h], 0.f);
                    float v1 = fmaxf(acc[i][j][2 * h + 1], 0.f);
                    red_add_v2(dst + col, v0, v1);
                }
            }
        }
    }
}

// ---------------------------------------------------------------------------
// LayerNorm: out = gamma * (h - mu) * rsqrt(var + eps) + beta, h = aggr + x
// ---------------------------------------------------------------------------
__global__ __launch_bounds__(256)
void ln_kernel(const float* __restrict__ x,
               const float* __restrict__ gamma,
               const float* __restrict__ beta,
               float* __restrict__ out) {
    const int gwarp = (blockIdx.x * blockDim.x + threadIdx.x) >> 5;
    const int lane = threadIdx.x & 31;
    if (gwarp >= N_NODES) return;

    const int c = lane * 4;
    float4 ag = *(const float4*)(g_aggr + (size_t)gwarp * HDIM + c);
    float4 xv = *(const float4*)(x + (size_t)gwarp * HDIM + c);
    float4 h = make_float4(ag.x + xv.x, ag.y + xv.y, ag.z + xv.z, ag.w + xv.w);

    float s = h.x + h.y + h.z + h.w;
    float ss = h.x * h.x + h.y * h.y + h.z * h.z + h.w * h.w;
    #pragma unroll
    for (int off = 16; off > 0; off >>= 1) {
        s += __shfl_xor_sync(0xffffffff, s, off);
        ss += __shfl_xor_sync(0xffffffff, ss, off);
    }
    const float mean = s * (1.f / HDIM);
    const float var = ss * (1.f / HDIM) - mean * mean;
    const float inv = rsqrtf(var + LN_EPS);

    float4 g = *(const float4*)(gamma + c);
    float4 b = *(const float4*)(beta + c);
    float4 o;
    o.x = g.x * (h.x - mean) * inv + b.x;
    o.y = g.y * (h.y - mean) * inv + b.y;
    o.z = g.z * (h.z - mean) * inv + b.z;
    o.w = g.w * (h.w - mean) * inv + b.w;
    *(float4*)(out + (size_t)gwarp * HDIM + c) = o;
}

// ---------------------------------------------------------------------------
extern "C" void kernel_launch(void* const* d_in, const int* in_sizes, int n_in,
                              void* d_out, int out_size) {
    const float* x         = (const float*)d_in[0];
    const int*   senders   = (const int*)d_in[1];
    const int*   receivers = (const int*)d_in[2];
    const float* ef        = (const float*)d_in[3];
    const float* W1        = (const float*)d_in[4];
    const float* b1        = (const float*)d_in[5];
    const float* gamma     = (const float*)d_in[6];
    const float* beta      = (const float*)d_in[7];
    float* out = (float*)d_out;

    void* aggr_ptr = nullptr;
    cudaGetSymbolAddress(&aggr_ptr, g_aggr);
    cudaMemsetAsync(aggr_ptr, 0, (size_t)N_NODES * HDIM * sizeof(float), 0);

    const size_t smem_np = (size_t)(32768 + 128 * SAW) * sizeof(float);   // ~199 KB
    const size_t smem_ed = (size_t)(128 + 16384) * sizeof(float);         // 66 KB -> 2 CTAs/SM
    cudaFuncSetAttribute(nodeproj_kernel, cudaFuncAttributeMaxDynamicSharedMemorySize, (int)smem_np);
    cudaFuncSetAttribute(edge_kernel, cudaFuncAttributeMaxDynamicSharedMemorySize, (int)smem_ed);

    nodeproj_kernel<<<148, 512, smem_np>>>(x, W1);
    edge_kernel<<<296, 256, smem_ed>>>(ef, senders, receivers, W1, b1);
    ln_kernel<<<(N_NODES + 7) / 8, 256>>>(x, gamma, beta, out);
}

// round 16
// speedup vs baseline: 1.3742x; 1.0138x over previous
#include <cuda_runtime.h>
#include <cuda_bf16.h>
#include <mma.h>
#include <cstdint>
#include <cstddef>

#define N_NODES 50000
#define N_NODES_PAD 50048          // 391 tiles * 128
#define N_EDGES 800000
#define HDIM 128
#define LN_EPS 1e-5f
#define N_TILES (N_EDGES / 128)
#define NP_TILES ((N_NODES + 127) / 128)

// Scratch (allocation-free rule: __device__ globals)
__device__ float g_xsxr[(size_t)N_NODES_PAD * 256];  // [n,0:128]=x@Ws, [n,128:256]=x@Wr
__device__ float g_aggr[(size_t)N_NODES * HDIM];

__device__ __forceinline__ float t32(float v) { return nvcuda::wmma::__float_to_tf32(v); }

__device__ __forceinline__ void red_add_v2(float* p, float a, float b) {
    asm volatile("red.global.add.v2.f32 [%0], {%1, %2};"
                 :: "l"(p), "f"(a), "f"(b) : "memory");
}

__device__ __forceinline__ void mma_16n8k8(float* c, const uint32_t* a, const uint32_t* b) {
    asm volatile(
        "mma.sync.aligned.m16n8k8.row.col.f32.tf32.tf32.f32 "
        "{%0,%1,%2,%3}, {%4,%5,%6,%7}, {%8,%9}, {%0,%1,%2,%3};"
        : "+f"(c[0]), "+f"(c[1]), "+f"(c[2]), "+f"(c[3])
        : "r"(a[0]), "r"(a[1]), "r"(a[2]), "r"(a[3]), "r"(b[0]), "r"(b[1]));
}

// B fragment-major staging: frag block (ks=k>>3, nt=n>>3) is 64 floats:
// lane = (n&7)*4 + (k&3), reg = (k&7)>>2.
__device__ __forceinline__ int bfrag_off(int k, int n, int NT) {
    int ks = k >> 3, nt = n >> 3;
    int lane = ((n & 7) << 2) | (k & 3);
    int reg = (k & 7) >> 2;
    return ((ks * NT + nt) << 6) + lane * 2 + reg;
}

// K-permutation so A fragments load as LDG.128:
// true col 16p + 4*tq + e  ->  frag 2p + (e>>1), slot tq + 4*(e&1)
__device__ __forceinline__ int kperm(int k) {
    int p = k >> 4, k16 = k & 15;
    int tq = k16 >> 2, e = k16 & 3;
    int f = 2 * p + (e >> 1);
    int slot = tq + 4 * (e & 1);
    return 8 * f + slot;
}

// ---------------------------------------------------------------------------
// Node projection v2 (barrier-free, edge-kernel style):
// 296 CTAs x 256 thr, 2 CTAs/SM. CTA parity selects col-half:
//   colHalf 0 -> Ws = W1[k][n],  colHalf 1 -> Wr = W1[128+k][n]
// B half staged frag-major (64 KB) with kperm; A = x rows straight from
// global as LDG.128 per kstep-pair. Warp tile 32 rows x 64 cols.
// Prologue also zeroes g_aggr (replaces the separate memset launch).
// ---------------------------------------------------------------------------
__global__ __launch_bounds__(256, 2)
void nodeproj_kernel(const float* __restrict__ x, const float* __restrict__ W1) {
    extern __shared__ float sm[];
    float* sB = sm;                          // 16 ks * 16 nt * 64 = 16384 floats

    const int tid = threadIdx.x;
    const int w = tid >> 5;
    const int lane = tid & 31;
    const int wr = w >> 1;                   // 0..3 : 32-row strip
    const int wc = w & 1;                    // 0..1 : 64-col half (within this 128-col half)
    const int g = lane >> 2;
    const int tq = lane & 3;
    const int t2 = 2 * tq;
    const int colHalf = blockIdx.x & 1;

    // zero g_aggr (grid-stride float4)
    {
        float4 z = make_float4(0.f, 0.f, 0.f, 0.f);
        float4* a4 = (float4*)g_aggr;
        const int total = N_NODES * HDIM / 4;
        for (int i = blockIdx.x * 256 + tid; i < total; i += 296 * 256) a4[i] = z;
    }

    // stage B half, frag-major with kperm
    for (int idx = tid; idx < 128 * 128; idx += 256) {
        int k = idx >> 7, n = idx & 127;
        float v = colHalf ? W1[(size_t)(128 + k) * HDIM + n]
                          : W1[(size_t)k * HDIM + n];
        sB[bfrag_off(kperm(k), n, 16)] = t32(v);
    }
    __syncthreads();

    const float2* pB = (const float2*)sB;

    for (int t = blockIdx.x >> 1; t < NP_TILES; t += 148) {
        const int rowBase = t * 128;
        const int row0 = rowBase + wr * 32 + g;

        // clamped source rows (tail tile reads clamp; writes land in pad rows)
        const float* rp[4];
        #pragma unroll
        for (int q = 0; q < 4; ++q) {
            int rr = row0 + (q >> 1) * 16 + (q & 1) * 8;
            if (rr >= N_NODES) rr = N_NODES - 1;
            rp[q] = x + (size_t)rr * HDIM + 4 * tq;
        }

        float acc[2][8][4];
        #pragma unroll
        for (int i = 0; i < 2; ++i)
            #pragma unroll
            for (int j = 0; j < 8; ++j)
                acc[i][j][0] = acc[i][j][1] = acc[i][j][2] = acc[i][j][3] = 0.f;

        #pragma unroll
        for (int p = 0; p < 8; ++p) {
            float4 v[2][2];
            #pragma unroll
            for (int i = 0; i < 2; ++i) {
                v[i][0] = *(const float4*)(rp[2 * i] + 16 * p);
                v[i][1] = *(const float4*)(rp[2 * i + 1] + 16 * p);
            }
            #pragma unroll
            for (int half = 0; half < 2; ++half) {
                int ks = 2 * p + half;
                uint32_t a[2][4], b[8][2];
                #pragma unroll
                for (int i = 0; i < 2; ++i) {
                    float e0 = half ? v[i][0].z : v[i][0].x;
                    float e1 = half ? v[i][0].w : v[i][0].y;
                    float f0 = half ? v[i][1].z : v[i][1].x;
                    float f1 = half ? v[i][1].w : v[i][1].y;
                    a[i][0] = __float_as_uint(t32(e0));
                    a[i][1] = __float_as_uint(t32(f0));
                    a[i][2] = __float_as_uint(t32(e1));
                    a[i][3] = __float_as_uint(t32(f1));
                }
                #pragma unroll
                for (int j = 0; j < 8; ++j) {
                    float2 bb = pB[(ks * 16 + wc * 8 + j) * 32 + lane];
                    b[j][0] = __float_as_uint(bb.x);
                    b[j][1] = __float_as_uint(bb.y);
                }
                #pragma unroll
                for (int i = 0; i < 2; ++i)
                    #pragma unroll
                    for (int j = 0; j < 8; ++j) mma_16n8k8(acc[i][j], a[i], b[j]);
            }
        }

        // store to g_xsxr: row = row0 + 16i + 8h, col = colHalf*128 + wc*64 + j*8 + t2
        #pragma unroll
        for (int i = 0; i < 2; ++i) {
            #pragma unroll
            for (int h = 0; h < 2; ++h) {
                int row = row0 + i * 16 + h * 8;
                float* dst = g_xsxr + (size_t)row * 256 + colHalf * 128 + wc * 64 + t2;
                #pragma unroll
                for (int j = 0; j < 8; ++j)
                    *(float2*)(dst + j * 8) = make_float2(acc[i][j][2 * h], acc[i][j][2 * h + 1]);
            }
        }
    }
}

// ---------------------------------------------------------------------------
// Fused edge kernel (UNCHANGED from R12 winner): barrier-free, K-permuted A/B,
// 256 thr = 8 independent warps, warp tile 32 edges x 64 cols, 2 CTAs/SM.
// ---------------------------------------------------------------------------
__global__ __launch_bounds__(256, 2)
void edge_kernel(const float* __restrict__ ef,
                 const int* __restrict__ senders,
                 const int* __restrict__ receivers,
                 const float* __restrict__ W1,
                 const float* __restrict__ b1) {
    extern __shared__ float sm[];
    float* sBias = sm;                       // 128
    float* sB = sm + 128;                    // 16 ks * 16 nt * 64 = 16384 (frag-major)

    const int tid = threadIdx.x;
    const int w = tid >> 5;
    const int lane = tid & 31;
    const int wr = w >> 1;                   // 0..3 : 32-edge strip
    const int wc = w & 1;                    // 0..1 : 64-col half
    const int g = lane >> 2;
    const int tq = lane & 3;
    const int t2 = 2 * tq;

    if (tid < 128) sBias[tid] = b1[tid];
    for (int idx = tid; idx < 128 * 128; idx += 256) {
        int k = idx >> 7, n = idx & 127;
        sB[bfrag_off(kperm(k), n, 16)] = t32(W1[(size_t)(256 + k) * HDIM + n]);
    }
    __syncthreads();

    const float2* pB = (const float2*)sB;

    for (int tile = blockIdx.x; tile < N_TILES; tile += gridDim.x) {
        const int base = tile * 128;
        const int row0 = base + wr * 32 + g;

        int sarr[4], rarr[4];
        #pragma unroll
        for (int i = 0; i < 2; ++i) {
            sarr[2 * i]     = senders[row0 + i * 16];
            rarr[2 * i]     = receivers[row0 + i * 16];
            sarr[2 * i + 1] = senders[row0 + i * 16 + 8];
            rarr[2 * i + 1] = receivers[row0 + i * 16 + 8];
        }

        float acc[2][8][4];
        #pragma unroll
        for (int i = 0; i < 2; ++i) {
            #pragma unroll
            for (int h = 0; h < 2; ++h) {
                const float* xsp = g_xsxr + (size_t)sarr[2 * i + h] * 256;
                const float* xrp = g_xsxr + (size_t)rarr[2 * i + h] * 256 + 128;
                #pragma unroll
                for (int j = 0; j < 8; ++j) {
                    int col = wc * 64 + j * 8 + t2;
                    float2 a_ = *(const float2*)(xsp + col);
                    float2 b_ = *(const float2*)(xrp + col);
                    float2 bb = *(const float2*)(sBias + col);
                    acc[i][j][2 * h]     = a_.x + b_.x + bb.x;
                    acc[i][j][2 * h + 1] = a_.y + b_.y + bb.y;
                }
            }
        }

        const float* Ab = ef + (size_t)row0 * HDIM + 4 * tq;
        #pragma unroll
        for (int p = 0; p < 8; ++p) {
            float4 v[2][2];
            #pragma unroll
            for (int i = 0; i < 2; ++i) {
                v[i][0] = *(const float4*)(Ab + i * (16 * HDIM) + 16 * p);
                v[i][1] = *(const float4*)(Ab + i * (16 * HDIM) + 8 * HDIM + 16 * p);
            }
            #pragma unroll
            for (int half = 0; half < 2; ++half) {
                int ks = 2 * p + half;
                uint32_t a[2][4], b[8][2];
                #pragma unroll
                for (int i = 0; i < 2; ++i) {
                    float e0 = half ? v[i][0].z : v[i][0].x;
                    float e1 = half ? v[i][0].w : v[i][0].y;
                    float f0 = half ? v[i][1].z : v[i][1].x;
                    float f1 = half ? v[i][1].w : v[i][1].y;
                    a[i][0] = __float_as_uint(t32(e0));
                    a[i][1] = __float_as_uint(t32(f0));
                    a[i][2] = __float_as_uint(t32(e1));
                    a[i][3] = __float_as_uint(t32(f1));
                }
                #pragma unroll
                for (int j = 0; j < 8; ++j) {
                    float2 bb = pB[(ks * 16 + wc * 8 + j) * 32 + lane];
                    b[j][0] = __float_as_uint(bb.x);
                    b[j][1] = __float_as_uint(bb.y);
                }
                #pragma unroll
                for (int i = 0; i < 2; ++i)
                    #pragma unroll
                    for (int j = 0; j < 8; ++j) mma_16n8k8(acc[i][j], a[i], b[j]);
            }
        }

        #pragma unroll
        for (int i = 0; i < 2; ++i) {
            #pragma unroll
            for (int h = 0; h < 2; ++h) {
                float* dst = g_aggr + (size_t)rarr[2 * i + h] * HDIM;
                #pragma unroll
                for (int j = 0; j < 8; ++j) {
                    int col = wc * 64 + j * 8 + t2;
                    float v0 = fmaxf(acc[i][j][2 * h], 0.f);
                    float v1 = fmaxf(acc[i][j][2 * h + 1], 0.f);
                    red_add_v2(dst + col, v0, v1);
                }
            }
        }
    }
}

// ---------------------------------------------------------------------------
// LayerNorm: out = gamma * (h - mu) * rsqrt(var + eps) + beta, h = aggr + x
// ---------------------------------------------------------------------------
__global__ __launch_bounds__(256)
void ln_kernel(const float* __restrict__ x,
               const float* __restrict__ gamma,
               const float* __restrict__ beta,
               float* __restrict__ out) {
    const int gwarp = (blockIdx.x * blockDim.x + threadIdx.x) >> 5;
    const int lane = threadIdx.x & 31;
    if (gwarp >= N_NODES) return;

    const int c = lane * 4;
    float4 ag = *(const float4*)(g_aggr + (size_t)gwarp * HDIM + c);
    float4 xv = *(const float4*)(x + (size_t)gwarp * HDIM + c);
    float4 h = make_float4(ag.x + xv.x, ag.y + xv.y, ag.z + xv.z, ag.w + xv.w);

    float s = h.x + h.y + h.z + h.w;
    float ss = h.x * h.x + h.y * h.y + h.z * h.z + h.w * h.w;
    #pragma unroll
    for (int off = 16; off > 0; off >>= 1) {
        s += __shfl_xor_sync(0xffffffff, s, off);
        ss += __shfl_xor_sync(0xffffffff, ss, off);
    }
    const float mean = s * (1.f / HDIM);
    const float var = ss * (1.f / HDIM) - mean * mean;
    const float inv = rsqrtf(var + LN_EPS);

    float4 g = *(const float4*)(gamma + c);
    float4 b = *(const float4*)(beta + c);
    float4 o;
    o.x = g.x * (h.x - mean) * inv + b.x;
    o.y = g.y * (h.y - mean) * inv + b.y;
    o.z = g.z * (h.z - mean) * inv + b.z;
    o.w = g.w * (h.w - mean) * inv + b.w;
    *(float4*)(out + (size_t)gwarp * HDIM + c) = o;
}

// ---------------------------------------------------------------------------
extern "C" void kernel_launch(void* const* d_in, const int* in_sizes, int n_in,
                              void* d_out, int out_size) {
    const float* x         = (const float*)d_in[0];
    const int*   senders   = (const int*)d_in[1];
    const int*   receivers = (const int*)d_in[2];
    const float* ef        = (const float*)d_in[3];
    const float* W1        = (const float*)d_in[4];
    const float* b1        = (const float*)d_in[5];
    const float* gamma     = (const float*)d_in[6];
    const float* beta      = (const float*)d_in[7];
    float* out = (float*)d_out;

    const size_t smem_np = (size_t)16384 * sizeof(float);           // 64 KB -> 2 CTAs/SM
    const size_t smem_ed = (size_t)(128 + 16384) * sizeof(float);   // 66 KB -> 2 CTAs/SM
    cudaFuncSetAttribute(nodeproj_kernel, cudaFuncAttributeMaxDynamicSharedMemorySize, (int)smem_np);
    cudaFuncSetAttribute(edge_kernel, cudaFuncAttributeMaxDynamicSharedMemorySize, (int)smem_ed);

    nodeproj_kernel<<<296, 256, smem_np>>>(x, W1);   // also zeroes g_aggr
    edge_kernel<<<296, 256, smem_ed>>>(ef, senders, receivers, W1, b1);
    ln_kernel<<<(N_NODES + 7) / 8, 256>>>(x, gamma, beta, out);
}